// round 16
// baseline (speedup 1.0000x reference)
#include <cuda_runtime.h>
#include <cuda_bf16.h>
#include <cstdint>
#include <math.h>

#define NN 100000
#define EE 3200000
#define FF 128

// ---------------- static device scratch (no allocations allowed) ----------------
__device__ __nv_bfloat16 g_xb[NN * FF];   // bf16 gather source (x, then h1*outnorm)
__device__ __nv_bfloat16 g_aggb[NN * FF]; // bf16 aggregation output
__device__ __nv_bfloat16 g_hb[NN * FF];   // conv2 output
__device__ __nv_bfloat16 g_mb[NN * FF];   // mlp hidden
__device__ __nv_bfloat16 g_w1t[FF * FF];  // W1^T bf16 [n][k]
__device__ __nv_bfloat16 g_w2t[FF * FF];
__device__ __nv_bfloat16 g_wm1t[FF * FF];
__device__ __nv_bfloat16 g_wm2t[64 * FF];
__device__ float g_outnorm[NN];
__device__ float g_innorm[NN];
__device__ int   g_outdeg[NN];
__device__ int   g_indeg[NN];
__device__ int   g_rowptr[NN + 1];
__device__ int   g_cursor[NN];
__device__ int   g_partial[128];
__device__ int   g_csrc[EE];              // CSR (by dst) column indices = src nodes

// ---------------- packed f32x2 helpers ----------------
__device__ __forceinline__ unsigned prmt0(unsigned a, unsigned sel) {
    unsigned r;
    asm("prmt.b32 %0, %1, 0, %2;" : "=r"(r) : "r"(a), "r"(sel));
    return r;
}
__device__ __forceinline__ unsigned long long pack64(unsigned lo, unsigned hi) {
    unsigned long long r;
    asm("mov.b64 %0, {%1, %2};" : "=l"(r) : "r"(lo), "r"(hi));
    return r;
}
__device__ __forceinline__ unsigned long long pack2_dup(float x) {
    unsigned long long r;
    asm("mov.b64 %0, {%1, %1};" : "=l"(r) : "r"(__float_as_uint(x)));
    return r;
}
__device__ __forceinline__ void add2(unsigned long long& d, unsigned long long a) {
    asm("add.rn.f32x2 %0, %0, %1;" : "+l"(d) : "l"(a));
}
__device__ __forceinline__ void fma2(unsigned long long& d, unsigned long long a, unsigned long long b) {
    asm("fma.rn.f32x2 %0, %1, %2, %0;" : "+l"(d) : "l"(a), "l"(b));
}
__device__ __forceinline__ float2 unpack2(unsigned long long v) {
    unsigned lo, hi;
    asm("mov.b64 {%0, %1}, %2;" : "=r"(lo), "=r"(hi) : "l"(v));
    float2 r; r.x = __uint_as_float(lo); r.y = __uint_as_float(hi);
    return r;
}

// ---------------- prep: zero counters + weight transpose/bf16 + x->bf16 ----------------
__global__ void __launch_bounds__(256) prep_kernel(
    const float4* __restrict__ x,
    const float* __restrict__ W1, const float* __restrict__ W2,
    const float* __restrict__ Wm1, const float* __restrict__ Wm2) {
    int i = blockIdx.x * blockDim.x + threadIdx.x;
    if (i < NN) { g_outdeg[i] = 0; g_indeg[i] = 0; }
    if (i < 16384) {
        int k = i >> 7, n = i & 127;
        g_w1t[n * 128 + k] = __float2bfloat16(W1[i]);
        g_w2t[n * 128 + k] = __float2bfloat16(W2[i]);
        g_wm1t[n * 128 + k] = __float2bfloat16(Wm1[i]);
        if (i < 8192) {
            int k2 = i >> 6, n2 = i & 63;
            g_wm2t[n2 * 128 + k2] = __float2bfloat16(Wm2[i]);
        }
    }
    if (i < NN * 32) {
        float4 v = x[i];
        __nv_bfloat162 b0 = __floats2bfloat162_rn(v.x, v.y);
        __nv_bfloat162 b1 = __floats2bfloat162_rn(v.z, v.w);
        uint2 p;
        p.x = *reinterpret_cast<unsigned*>(&b0);
        p.y = *reinterpret_cast<unsigned*>(&b1);
        ((uint2*)g_xb)[i] = p;
    }
}

// ---------------- graph preprocessing ----------------
__global__ void __launch_bounds__(256) degree_kernel(const int* __restrict__ src, const int* __restrict__ dst) {
    int e = blockIdx.x * blockDim.x + threadIdx.x;
    if (e < EE) {
        atomicAdd(&g_outdeg[src[e]], 1);
        atomicAdd(&g_indeg[dst[e]], 1);
    }
}

__global__ void __launch_bounds__(256) scan_reduce_kernel() {
    __shared__ int s[256];
    int t = threadIdx.x;
    int base = blockIdx.x * 1024;
    int v = 0;
#pragma unroll
    for (int j = 0; j < 4; j++) {
        int i = base + t + j * 256;
        if (i < NN) v += g_indeg[i];
    }
    s[t] = v;
    __syncthreads();
    for (int off = 128; off > 0; off >>= 1) {
        if (t < off) s[t] += s[t + off];
        __syncthreads();
    }
    if (t == 0) g_partial[blockIdx.x] = s[0];
}

__global__ void __launch_bounds__(1024) scan_down_kernel(int nparts) {
    __shared__ int part[128];
    __shared__ int orig[128];
    __shared__ int s[1024];
    int t = threadIdx.x;
    if (t < 128) {
        int v = (t < nparts) ? g_partial[t] : 0;
        part[t] = v; orig[t] = v;
    }
    __syncthreads();
    for (int off = 1; off < 128; off <<= 1) {
        int u = (t < 128 && t >= off) ? part[t - off] : 0;
        __syncthreads();
        if (t < 128) part[t] += u;
        __syncthreads();
    }
    int blk_off = part[blockIdx.x] - orig[blockIdx.x];  // exclusive prefix

    int i = blockIdx.x * 1024 + t;
    int d = (i < NN) ? g_indeg[i] : 0;
    s[t] = d;
    __syncthreads();
    for (int off = 1; off < 1024; off <<= 1) {
        int u = (t >= off) ? s[t - off] : 0;
        __syncthreads();
        s[t] += u;
        __syncthreads();
    }
    if (i < NN) {
        int rp = s[t] - d + blk_off;
        g_rowptr[i] = rp;
        g_cursor[i] = rp;
        g_innorm[i]  = rsqrtf((float)max(d, 1));
        g_outnorm[i] = rsqrtf((float)max(g_outdeg[i], 1));
    }
    if (i == 0) g_rowptr[NN] = EE;
}

__global__ void __launch_bounds__(256) fill_kernel(const int* __restrict__ src, const int* __restrict__ dst) {
    int e = blockIdx.x * blockDim.x + threadIdx.x;
    if (e < EE) {
        int pos = atomicAdd(&g_cursor[dst[e]], 1);
        g_csrc[pos] = src[e];
    }
}

// ---------------- aggregation: TWO nodes per warp (16-lane halves), uint4 gather ----------------
// Each lane covers 8 feats: [lane16*8, lane16*8+8). Per edge: one uint4 (16B) per lane.
// bf16->f32 via PRMT zero-extend (bit-exact).
#define SEL_LO 0x1044u
#define SEL_HI 0x3244u

template <bool SCALE>
__global__ void __launch_bounds__(256) agg_kernel() {
    int w = (blockIdx.x * blockDim.x + threadIdx.x) >> 4;  // node = global 16-lane half
    if (w >= NN) return;
    int lane16 = threadIdx.x & 15;
    int s = g_rowptr[w], e = g_rowptr[w + 1];
    const uint4* __restrict__ X = (const uint4*)g_xb;  // row = 16 uint4
    unsigned long long a01 = 0ull, a23 = 0ull, a45 = 0ull, a67 = 0ull;
    int j = s;
    for (; j + 3 < e; j += 4) {
        int us[4];
#pragma unroll
        for (int q = 0; q < 4; q++) us[q] = g_csrc[j + q];
        uint4 vs[4];
#pragma unroll
        for (int q = 0; q < 4; q++) vs[q] = X[us[q] * 16 + lane16];
        float ns[4];
        if (SCALE) {
#pragma unroll
            for (int q = 0; q < 4; q++) ns[q] = g_outnorm[us[q]];
        }
#pragma unroll
        for (int q = 0; q < 4; q++) {
            unsigned long long p01 = pack64(prmt0(vs[q].x, SEL_LO), prmt0(vs[q].x, SEL_HI));
            unsigned long long p23 = pack64(prmt0(vs[q].y, SEL_LO), prmt0(vs[q].y, SEL_HI));
            unsigned long long p45 = pack64(prmt0(vs[q].z, SEL_LO), prmt0(vs[q].z, SEL_HI));
            unsigned long long p67 = pack64(prmt0(vs[q].w, SEL_LO), prmt0(vs[q].w, SEL_HI));
            if (SCALE) {
                unsigned long long nn = pack2_dup(ns[q]);
                fma2(a01, p01, nn); fma2(a23, p23, nn);
                fma2(a45, p45, nn); fma2(a67, p67, nn);
            } else {
                add2(a01, p01); add2(a23, p23);
                add2(a45, p45); add2(a67, p67);
            }
        }
    }
    for (; j < e; j++) {
        int u = g_csrc[j];
        uint4 v = X[u * 16 + lane16];
        unsigned long long p01 = pack64(prmt0(v.x, SEL_LO), prmt0(v.x, SEL_HI));
        unsigned long long p23 = pack64(prmt0(v.y, SEL_LO), prmt0(v.y, SEL_HI));
        unsigned long long p45 = pack64(prmt0(v.z, SEL_LO), prmt0(v.z, SEL_HI));
        unsigned long long p67 = pack64(prmt0(v.w, SEL_LO), prmt0(v.w, SEL_HI));
        if (SCALE) {
            unsigned long long nn = pack2_dup(g_outnorm[u]);
            fma2(a01, p01, nn); fma2(a23, p23, nn);
            fma2(a45, p45, nn); fma2(a67, p67, nn);
        } else {
            add2(a01, p01); add2(a23, p23);
            add2(a45, p45); add2(a67, p67);
        }
    }
    float inw = g_innorm[w];
    float2 f01 = unpack2(a01), f23 = unpack2(a23), f45 = unpack2(a45), f67 = unpack2(a67);
    __nv_bfloat162 b0 = __floats2bfloat162_rn(f01.x * inw, f01.y * inw);
    __nv_bfloat162 b1 = __floats2bfloat162_rn(f23.x * inw, f23.y * inw);
    __nv_bfloat162 b2 = __floats2bfloat162_rn(f45.x * inw, f45.y * inw);
    __nv_bfloat162 b3 = __floats2bfloat162_rn(f67.x * inw, f67.y * inw);
    uint4 p;
    p.x = *reinterpret_cast<unsigned*>(&b0);
    p.y = *reinterpret_cast<unsigned*>(&b1);
    p.z = *reinterpret_cast<unsigned*>(&b2);
    p.w = *reinterpret_cast<unsigned*>(&b3);
    ((uint4*)g_aggb)[w * 16 + lane16] = p;
}

// ---------------- mma.sync bf16 GEMM (R10: direct LDS fragment loads) ----------------
template <int NR, int MODE, bool OUTB, bool POST>
__global__ void __launch_bounds__(256) mma_gemm_kernel(
    const __nv_bfloat16* __restrict__ A,
    const __nv_bfloat16* __restrict__ Bt,
    const float* __restrict__ bias,
    const float* __restrict__ postscale,
    void* __restrict__ outp, int M)
{
    constexpr int K = 128;
    constexpr int SA = 136;                // row stride in bf16 elems (+16B pad -> conflict-free frags)
    constexpr int NT = NR / 16;            // n-tiles (8 wide) per warp: 8 (NR=128) or 4 (NR=64)
    extern __shared__ char smem[];
    __nv_bfloat16* As = (__nv_bfloat16*)smem;                       // 128 x SA
    __nv_bfloat16* Bs = (__nv_bfloat16*)(smem + 128 * SA * 2);      // NR x SA
    float* bs = (float*)(smem + 128 * SA * 2 + NR * SA * 2);

    int tid = threadIdx.x;
    int brow = blockIdx.x * 128;

    // load A tile (uint4 per 8 elems)
    for (int i = tid; i < 128 * 16; i += 256) {
        int row = i >> 4, seg = i & 15;
        uint4 v = make_uint4(0u, 0u, 0u, 0u);
        int gr = brow + row;
        if (gr < M) v = *(const uint4*)(A + (size_t)gr * K + seg * 8);
        *(uint4*)(As + row * SA + seg * 8) = v;
    }
    // load B tile
    for (int i = tid; i < NR * 16; i += 256) {
        int row = i >> 4, seg = i & 15;
        *(uint4*)(Bs + row * SA + seg * 8) = *(const uint4*)(Bt + (size_t)row * K + seg * 8);
    }
    if (tid < NR) bs[tid] = bias[tid];
    __syncthreads();

    int wid = tid >> 5, lane = tid & 31;
    int wm = wid & 3, wn = wid >> 2;       // wm: 0..3 (32 rows each), wn: 0..1 (NR/2 cols each)
    int gid = lane >> 2, tig = lane & 3;

    float c[2][NT][4];
#pragma unroll
    for (int mt = 0; mt < 2; mt++)
#pragma unroll
        for (int nt = 0; nt < NT; nt++)
#pragma unroll
            for (int q = 0; q < 4; q++) c[mt][nt][q] = 0.f;

#pragma unroll
    for (int ks = 0; ks < 8; ks++) {
        int k0 = ks * 16;
        unsigned af[2][4];
#pragma unroll
        for (int mt = 0; mt < 2; mt++) {
            const __nv_bfloat16* p = As + (wm * 32 + mt * 16 + gid) * SA + k0 + tig * 2;
            af[mt][0] = *(const unsigned*)(p);
            af[mt][1] = *(const unsigned*)(p + 8 * SA);
            af[mt][2] = *(const unsigned*)(p + 8);
            af[mt][3] = *(const unsigned*)(p + 8 * SA + 8);
        }
        unsigned bf[NT][2];
#pragma unroll
        for (int nt = 0; nt < NT; nt++) {
            const __nv_bfloat16* q = Bs + (wn * (NT * 8) + nt * 8 + gid) * SA + k0 + tig * 2;
            bf[nt][0] = *(const unsigned*)(q);
            bf[nt][1] = *(const unsigned*)(q + 8);
        }
#pragma unroll
        for (int mt = 0; mt < 2; mt++)
#pragma unroll
            for (int nt = 0; nt < NT; nt++) {
                asm volatile(
                    "mma.sync.aligned.m16n8k16.row.col.f32.bf16.bf16.f32 "
                    "{%0,%1,%2,%3}, {%4,%5,%6,%7}, {%8,%9}, {%0,%1,%2,%3};"
                    : "+f"(c[mt][nt][0]), "+f"(c[mt][nt][1]),
                      "+f"(c[mt][nt][2]), "+f"(c[mt][nt][3])
                    : "r"(af[mt][0]), "r"(af[mt][1]), "r"(af[mt][2]), "r"(af[mt][3]),
                      "r"(bf[nt][0]), "r"(bf[nt][1]));
            }
    }

    // epilogue: c0,c1 -> (r, col..col+1); c2,c3 -> (r+8, col..col+1)
#pragma unroll
    for (int mt = 0; mt < 2; mt++) {
        int r0 = brow + wm * 32 + mt * 16 + gid;
        int r1 = r0 + 8;
        float p0 = 1.f, p1 = 1.f;
        if (POST) {
            if (r0 < M) p0 = postscale[r0];
            if (r1 < M) p1 = postscale[r1];
        }
#pragma unroll
        for (int nt = 0; nt < NT; nt++) {
            int col = wn * (NT * 8) + nt * 8 + tig * 2;
            float b0v = bs[col], b1v = bs[col + 1];
            float v0 = c[mt][nt][0] + b0v, v1 = c[mt][nt][1] + b1v;
            float v2 = c[mt][nt][2] + b0v, v3 = c[mt][nt][3] + b1v;
            if (MODE == 2) {
                v0 = 1.f / (1.f + __expf(-v0)); v1 = 1.f / (1.f + __expf(-v1));
                v2 = 1.f / (1.f + __expf(-v2)); v3 = 1.f / (1.f + __expf(-v3));
            } else {
                v0 = fmaxf(v0, 0.f) * p0; v1 = fmaxf(v1, 0.f) * p0;
                v2 = fmaxf(v2, 0.f) * p1; v3 = fmaxf(v3, 0.f) * p1;
            }
            if (OUTB) {
                __nv_bfloat16* ob = (__nv_bfloat16*)outp;
                if (r0 < M) {
                    __nv_bfloat162 pk = __floats2bfloat162_rn(v0, v1);
                    *(unsigned*)(ob + (size_t)r0 * NR + col) = *reinterpret_cast<unsigned*>(&pk);
                }
                if (r1 < M) {
                    __nv_bfloat162 pk = __floats2bfloat162_rn(v2, v3);
                    *(unsigned*)(ob + (size_t)r1 * NR + col) = *reinterpret_cast<unsigned*>(&pk);
                }
            } else {
                float* of = (float*)outp;
                if (r0 < M) *(float2*)(of + (size_t)r0 * NR + col) = make_float2(v0, v1);
                if (r1 < M) *(float2*)(of + (size_t)r1 * NR + col) = make_float2(v2, v3);
            }
        }
    }
}

// ---------------- launch ----------------
extern "C" void kernel_launch(void* const* d_in, const int* in_sizes, int n_in,
                              void* d_out, int out_size) {
    const float* x   = (const float*)d_in[0];
    const int*   src = (const int*)d_in[1];
    const int*   dst = (const int*)d_in[2];
    const float* W1  = (const float*)d_in[3];
    const float* b1  = (const float*)d_in[4];
    const float* W2  = (const float*)d_in[5];
    const float* b2  = (const float*)d_in[6];
    const float* Wm1 = (const float*)d_in[7];
    const float* bm1 = (const float*)d_in[8];
    const float* Wm2 = (const float*)d_in[9];
    const float* bm2 = (const float*)d_in[10];
    float* out = (float*)d_out;

    void *p_xb, *p_aggb, *p_hb, *p_mb, *p_w1t, *p_w2t, *p_wm1t, *p_wm2t, *p_outnorm;
    cudaGetSymbolAddress(&p_xb, g_xb);
    cudaGetSymbolAddress(&p_aggb, g_aggb);
    cudaGetSymbolAddress(&p_hb, g_hb);
    cudaGetSymbolAddress(&p_mb, g_mb);
    cudaGetSymbolAddress(&p_w1t, g_w1t);
    cudaGetSymbolAddress(&p_w2t, g_w2t);
    cudaGetSymbolAddress(&p_wm1t, g_wm1t);
    cudaGetSymbolAddress(&p_wm2t, g_wm2t);
    cudaGetSymbolAddress(&p_outnorm, g_outnorm);

    // smem: A 128*136*2 + B NR*136*2 + bias NR*4
    constexpr int SMEM_G128 = 128 * 136 * 2 + 128 * 136 * 2 + 512;  // 70144
    constexpr int SMEM_G64  = 128 * 136 * 2 + 64 * 136 * 2 + 256;   // 52480
    cudaFuncSetAttribute(mma_gemm_kernel<128, 0, true, true>,
                         cudaFuncAttributeMaxDynamicSharedMemorySize, SMEM_G128);
    cudaFuncSetAttribute(mma_gemm_kernel<128, 0, true, false>,
                         cudaFuncAttributeMaxDynamicSharedMemorySize, SMEM_G128);
    cudaFuncSetAttribute(mma_gemm_kernel<64, 2, false, false>,
                         cudaFuncAttributeMaxDynamicSharedMemorySize, SMEM_G64);

    const int TB = 256;
    int eblk = (EE + TB - 1) / TB;
    int sblk = (NN + 1023) / 1024;  // 98
    int gblk = (NN + 127) / 128;    // 782
    int ablk = (NN * 32 + TB - 1) / TB;
    int a2blk = (NN * 16 + TB - 1) / TB;   // two nodes per warp

    // prep (zero + weights + x->bf16), then graph preprocessing
    prep_kernel<<<ablk, TB>>>((const float4*)x, W1, W2, Wm1, Wm2);
    degree_kernel<<<eblk, TB>>>(src, dst);
    scan_reduce_kernel<<<sblk, 256>>>();
    scan_down_kernel<<<sblk, 1024>>>(sblk);
    fill_kernel<<<eblk, TB>>>(src, dst);

    // conv1
    agg_kernel<true><<<a2blk, TB>>>();
    mma_gemm_kernel<128, 0, true, true><<<gblk, 256, SMEM_G128>>>(
        (const __nv_bfloat16*)p_aggb, (const __nv_bfloat16*)p_w1t, b1,
        (const float*)p_outnorm, p_xb, NN);

    // conv2
    agg_kernel<false><<<a2blk, TB>>>();
    mma_gemm_kernel<128, 0, true, false><<<gblk, 256, SMEM_G128>>>(
        (const __nv_bfloat16*)p_aggb, (const __nv_bfloat16*)p_w2t, b2,
        nullptr, p_hb, NN);

    // MLP head
    mma_gemm_kernel<128, 0, true, false><<<gblk, 256, SMEM_G128>>>(
        (const __nv_bfloat16*)p_hb, (const __nv_bfloat16*)p_wm1t, bm1,
        nullptr, p_mb, NN);
    mma_gemm_kernel<64, 2, false, false><<<gblk, 256, SMEM_G64>>>(
        (const __nv_bfloat16*)p_mb, (const __nv_bfloat16*)p_wm2t, bm2,
        nullptr, out, NN);
}